// round 9
// baseline (speedup 1.0000x reference)
#include <cuda_runtime.h>
#include <cuda_fp16.h>
#include <cstdint>

#define D      128
#define TM     64
#define NMAX   50000
#define DEGMAX 128
#define EPS    1e-8f

#define ROWB  272           // bytes per fp16 tile row (136 halves)
#define SWF   132           // f32 staging stride

// ---------------- scratch (static device globals) ----------------
__device__ __half g_y[NMAX * D];            // fp16: halves gather traffic
__device__ int    g_hist[NMAX];             // in-degree (atomic counters)
__device__ int    g_csr[NMAX * DEGMAX];     // padded neighbor buckets
// transposed fp16 weights: [mat][n][k]; mat: 0=msg1,1=msg2,2=upd1,3=upd2
__device__ __half g_wt[4 * D * D];

// ---------------- smem layout (bytes) ----------------
#define OFF_AH 0u            /* 64 x 272  = 17408 */
#define OFF_AL 17408u
#define OFF_W1 34816u        /* 128 x 272 = 34816 */
#define OFF_W2 69632u
#define OFF_B1 104448u
#define OFF_B2 104960u
#define SMEM_DYN 105472u

// ---------------- PTX helpers ----------------
__device__ __forceinline__ uint32_t smem_u32(const void* p) {
    uint32_t a;
    asm("{ .reg .u64 t; cvta.to.shared.u64 t, %1; cvt.u32.u64 %0, t; }" : "=r"(a) : "l"(p));
    return a;
}
__device__ __forceinline__ void ldsm4(uint32_t* r, uint32_t addr) {
    asm volatile("ldmatrix.sync.aligned.m8n8.x4.shared.b16 {%0,%1,%2,%3}, [%4];"
        : "=r"(r[0]), "=r"(r[1]), "=r"(r[2]), "=r"(r[3]) : "r"(addr));
}
__device__ __forceinline__ void mma16816(float* c, const uint32_t* a,
                                         uint32_t b0, uint32_t b1) {
    asm("mma.sync.aligned.m16n8k16.row.col.f32.f16.f16.f32 "
        "{%0,%1,%2,%3}, {%4,%5,%6,%7}, {%8,%9}, {%0,%1,%2,%3};"
        : "+f"(c[0]), "+f"(c[1]), "+f"(c[2]), "+f"(c[3])
        : "r"(a[0]), "r"(a[1]), "r"(a[2]), "r"(a[3]), "r"(b0), "r"(b1));
}
__device__ __forceinline__ uint32_t packh2(__half a, __half b) {
    __half2 t = __halves2half2(a, b);
    return *(uint32_t*)&t;
}
#define CP_ASYNC16(dst, src) \
    asm volatile("cp.async.cg.shared.global [%0], [%1], 16;" :: "r"(dst), "l"(src))
#define CP_COMMIT() asm volatile("cp.async.commit_group;")
#define CP_WAIT0()  asm volatile("cp.async.wait_group 0;")

// 2-term fp16 split GEMM (M64 tile): acc += (Ah+Al) @ W^T
__device__ __forceinline__ void do_gemm(
    uint32_t sAH, uint32_t sAL, uint32_t sW,
    int wm, int wn, int lane, float acc[2][4][4])
{
    const uint32_t lrow = (uint32_t)(lane & 15) * ROWB + (uint32_t)(lane >> 4) * 16;
    const uint32_t aoff = (uint32_t)(wm * 32) * ROWB + lrow;
    const uint32_t woff = (uint32_t)(wn * 32) * ROWB + lrow;

    #pragma unroll
    for (int ks = 0; ks < 8; ks++) {
        const uint32_t kb = (uint32_t)ks * 32;
        uint32_t ah[2][4], al[2][4], wf[2][4];
        #pragma unroll
        for (int ms = 0; ms < 2; ms++) {
            ldsm4(ah[ms], sAH + aoff + ms * 16 * ROWB + kb);
            ldsm4(al[ms], sAL + aoff + ms * 16 * ROWB + kb);
        }
        #pragma unroll
        for (int np = 0; np < 2; np++)
            ldsm4(wf[np], sW + woff + np * 16 * ROWB + kb);
        #pragma unroll
        for (int np = 0; np < 2; np++)
            #pragma unroll
            for (int h = 0; h < 2; h++)
                #pragma unroll
                for (int ms = 0; ms < 2; ms++)
                    mma16816(acc[ms][np * 2 + h], ah[ms], wf[np][h], wf[np][h + 2]);
        #pragma unroll
        for (int np = 0; np < 2; np++)
            #pragma unroll
            for (int h = 0; h < 2; h++)
                #pragma unroll
                for (int ms = 0; ms < 2; ms++)
                    mma16816(acc[ms][np * 2 + h], al[ms], wf[np][h], wf[np][h + 2]);
    }
}

// ---------------- bucket-CSR build ----------------
__global__ void zero_hist_kernel(int n) {
    int i = blockIdx.x * blockDim.x + threadIdx.x;
    if (i < n) g_hist[i] = 0;
}
__global__ void fill_kernel(const int* __restrict__ ei, int E) {
    int e = blockIdx.x * blockDim.x + threadIdx.x;
    if (e < E) {
        int dst = ei[e];
        int src = ei[E + e];
        int pos = atomicAdd(&g_hist[dst], 1);
        if (pos < DEGMAX) g_csr[dst * DEGMAX + pos] = src;
    }
}

// transpose + fp16 convert of the 4 weight matrices
__global__ void prep_w_kernel(const float* __restrict__ w0, const float* __restrict__ w1,
                              const float* __restrict__ w2, const float* __restrict__ w3) {
    int g = blockIdx.x * blockDim.x + threadIdx.x;    // 0..16383
    int mat = g >> 12;
    int rem = g & 4095;
    int k = rem >> 5;
    int n4 = rem & 31;
    const float* W = (mat == 0) ? w0 : (mat == 1) ? w1 : (mat == 2) ? w2 : w3;
    float4 v = ((const float4*)W)[k * 32 + n4];
    float a[4] = {v.x, v.y, v.z, v.w};
    #pragma unroll
    for (int j = 0; j < 4; j++) {
        int n = n4 * 4 + j;
        g_wt[mat * D * D + n * D + k] = __float2half_rn(a[j]);
    }
}

// accumulate 4 fp16 pairs (uint2 = 4 halves) into float4
__device__ __forceinline__ void h2acc(float4& a, uint2 u) {
    __half2 p0 = *(__half2*)&u.x, p1 = *(__half2*)&u.y;
    float2 f0 = __half22float2(p0), f1 = __half22float2(p1);
    a.x += f0.x; a.y += f0.y; a.z += f1.x; a.w += f1.y;
}
__device__ __forceinline__ void f4add(float4& a, const float4 b) {
    a.x += b.x; a.y += b.y; a.z += b.z; a.w += b.w;
}

// ---------------- fused MLP via mma.sync (HMMA fp16), TM=64, 2 CTAs/SM ----------------
// mode 0: g_y = MLP1(logmap0(x))            (g_y stored fp16)
// mode 1: out = expmap0(MLP2(mean_{bucket} g_y[src]))
__global__ __launch_bounds__(256, 2) void mlp_tc_kernel(
    const float* __restrict__ xin,
    const float* __restrict__ B1v, const float* __restrict__ B2v,
    float* __restrict__ outp, int N, int mode)
{
    extern __shared__ char sb[];
    const uint32_t sbase = smem_u32(sb);
    float* B1s = (float*)(sb + OFF_B1);
    float* B2s = (float*)(sb + OFF_B2);

    const int tid  = threadIdx.x;
    const int wid  = tid >> 5;
    const int lane = tid & 31;
    const int gid  = lane >> 2;
    const int tig  = lane & 3;
    const int wm   = wid & 1;          // 2 x M32
    const int wn   = wid >> 1;         // 4 x N32
    const int row0 = blockIdx.x * TM;

    if (tid < 128) B1s[tid] = B1v[tid];
    else           B2s[tid - 128] = B2v[tid - 128];

    // ---- kick off W1+W2 loads via cp.async (overlaps with input phase) ----
    {
        int m1 = mode * 2, m2 = mode * 2 + 1;
        const float4* s1 = (const float4*)(g_wt + m1 * D * D);
        const float4* s2 = (const float4*)(g_wt + m2 * D * D);
        #pragma unroll
        for (int it = 0; it < 8; it++) {
            int idx = tid + it * 256;          // 2048 float4 per matrix
            int n = idx >> 4, c = idx & 15;
            CP_ASYNC16(sbase + OFF_W1 + n * ROWB + c * 16, (const void*)(s1 + idx));
            CP_ASYNC16(sbase + OFF_W2 + n * ROWB + c * 16, (const void*)(s2 + idx));
        }
        CP_COMMIT();
    }

    // ---- input rows: logmap0(x) (mode 0) or bucket-gather mean (mode 1) ----
    {
        const float4* x4 = (const float4*)xin;
        const uint2*  y2 = (const uint2*)g_y;       // fp16 rows: 32 x uint2
        #pragma unroll 2
        for (int i = 0; i < 8; i++) {
            int r = wid * 8 + i;
            int rg = row0 + r;
            float4 v = make_float4(0.f, 0.f, 0.f, 0.f);
            if (rg < N) {
                if (mode == 0) {
                    v = x4[rg * 32 + lane];
                    float ss = v.x * v.x + v.y * v.y + v.z * v.z + v.w * v.w;
                    #pragma unroll
                    for (int m = 16; m >= 1; m >>= 1) ss += __shfl_xor_sync(0xffffffffu, ss, m);
                    float nrm = sqrtf(ss);
                    float nc  = fminf(fmaxf(nrm, EPS), 1.0f - 1e-5f);
                    float f   = atanhf(nc) / nc;
                    v.x *= f; v.y *= f; v.z *= f; v.w *= f;
                } else {
                    const int* nb = g_csr + rg * DEGMAX;
                    int deg = g_hist[rg];
                    if (deg > DEGMAX) deg = DEGMAX;
                    float4 v1 = make_float4(0.f, 0.f, 0.f, 0.f);
                    float4 v2 = make_float4(0.f, 0.f, 0.f, 0.f);
                    float4 v3 = make_float4(0.f, 0.f, 0.f, 0.f);
                    int j = 0;
                    for (; j + 4 <= deg; j += 4) {
                        int s0 = nb[j], s1 = nb[j + 1], s2 = nb[j + 2], s3 = nb[j + 3];
                        h2acc(v,  y2[s0 * 32 + lane]);
                        h2acc(v1, y2[s1 * 32 + lane]);
                        h2acc(v2, y2[s2 * 32 + lane]);
                        h2acc(v3, y2[s3 * 32 + lane]);
                    }
                    for (; j < deg; j++)
                        h2acc(v, y2[nb[j] * 32 + lane]);
                    f4add(v1, v2); f4add(v, v3); f4add(v, v1);
                    float inv = 1.0f / ((float)g_hist[rg] + EPS);
                    v.x *= inv; v.y *= inv; v.z *= inv; v.w *= inv;
                }
            }
            // fp16 hi/lo split of A
            __half h0 = __float2half_rn(v.x), h1 = __float2half_rn(v.y);
            __half h2 = __float2half_rn(v.z), h3 = __float2half_rn(v.w);
            __half l0 = __float2half_rn(v.x - __half2float(h0));
            __half l1 = __float2half_rn(v.y - __half2float(h1));
            __half l2 = __float2half_rn(v.z - __half2float(h2));
            __half l3 = __float2half_rn(v.w - __half2float(h3));
            *(uint2*)(sb + OFF_AH + r * ROWB + lane * 8) =
                make_uint2(packh2(h0, h1), packh2(h2, h3));
            *(uint2*)(sb + OFF_AL + r * ROWB + lane * 8) =
                make_uint2(packh2(l0, l1), packh2(l2, l3));
        }
    }
    CP_WAIT0();
    __syncthreads();

    float acc[2][4][4];

    // ---- GEMM1 ----
    #pragma unroll
    for (int ms = 0; ms < 2; ms++)
        #pragma unroll
        for (int ns = 0; ns < 4; ns++)
            #pragma unroll
            for (int j = 0; j < 4; j++) acc[ms][ns][j] = 0.f;
    do_gemm(sbase + OFF_AH, sbase + OFF_AL, sbase + OFF_W1, wm, wn, lane, acc);
    __syncthreads();

    // ---- epilogue1: T = relu(acc + B1) -> Ah/Al (fp16 hi/lo) ----
    #pragma unroll
    for (int ms = 0; ms < 2; ms++) {
        int r = wm * 32 + ms * 16 + gid;
        #pragma unroll
        for (int ns = 0; ns < 4; ns++) {
            int col = wn * 32 + ns * 8 + tig * 2;
            float b0 = B1s[col], b1 = B1s[col + 1];
            float v0 = fmaxf(acc[ms][ns][0] + b0, 0.f);
            float v1 = fmaxf(acc[ms][ns][1] + b1, 0.f);
            float v2 = fmaxf(acc[ms][ns][2] + b0, 0.f);
            float v3 = fmaxf(acc[ms][ns][3] + b1, 0.f);
            __half a0 = __float2half_rn(v0), a1 = __float2half_rn(v1);
            __half a2 = __float2half_rn(v2), a3 = __float2half_rn(v3);
            __half c0 = __float2half_rn(v0 - __half2float(a0));
            __half c1 = __float2half_rn(v1 - __half2float(a1));
            __half c2 = __float2half_rn(v2 - __half2float(a2));
            __half c3 = __float2half_rn(v3 - __half2float(a3));
            *(uint32_t*)(sb + OFF_AH + r * ROWB + col * 2)       = packh2(a0, a1);
            *(uint32_t*)(sb + OFF_AL + r * ROWB + col * 2)       = packh2(c0, c1);
            *(uint32_t*)(sb + OFF_AH + (r + 8) * ROWB + col * 2) = packh2(a2, a3);
            *(uint32_t*)(sb + OFF_AL + (r + 8) * ROWB + col * 2) = packh2(c2, c3);
        }
    }
    __syncthreads();

    // ---- GEMM2 (W2 already resident) ----
    #pragma unroll
    for (int ms = 0; ms < 2; ms++)
        #pragma unroll
        for (int ns = 0; ns < 4; ns++)
            #pragma unroll
            for (int j = 0; j < 4; j++) acc[ms][ns][j] = 0.f;
    do_gemm(sbase + OFF_AH, sbase + OFF_AL, sbase + OFF_W2, wm, wn, lane, acc);

    if (mode == 0) {
        // write g_y in fp16 (half2 per 2 cols)
        __half2* yh = (__half2*)g_y;
        #pragma unroll
        for (int ms = 0; ms < 2; ms++) {
            int r = wm * 32 + ms * 16 + gid;
            #pragma unroll
            for (int ns = 0; ns < 4; ns++) {
                int col = wn * 32 + ns * 8 + tig * 2;
                float b0 = B2s[col], b1 = B2s[col + 1];
                int rg = row0 + r;
                if (rg < N)
                    yh[rg * 64 + (col >> 1)] =
                        __floats2half2_rn(acc[ms][ns][0] + b0, acc[ms][ns][1] + b1);
                if (rg + 8 < N)
                    yh[(rg + 8) * 64 + (col >> 1)] =
                        __floats2half2_rn(acc[ms][ns][2] + b0, acc[ms][ns][3] + b1);
            }
        }
    } else {
        __syncthreads();
        float* Sf = (float*)(sb + OFF_W1);        // reuse W1 region: 64 x 132 f32 staging
        #pragma unroll
        for (int ms = 0; ms < 2; ms++) {
            int r = wm * 32 + ms * 16 + gid;
            #pragma unroll
            for (int ns = 0; ns < 4; ns++) {
                int col = wn * 32 + ns * 8 + tig * 2;
                float b0 = B2s[col], b1 = B2s[col + 1];
                *(float2*)(Sf + r * SWF + col) =
                    make_float2(acc[ms][ns][0] + b0, acc[ms][ns][1] + b1);
                *(float2*)(Sf + (r + 8) * SWF + col) =
                    make_float2(acc[ms][ns][2] + b0, acc[ms][ns][3] + b1);
            }
        }
        __syncthreads();
        // expmap0: 4 threads per row
        int r = tid >> 2, q = tid & 3;
        float ss = 0.f;
        float4 vv[8];
        #pragma unroll
        for (int j = 0; j < 8; j++) {
            float4 v = *(float4*)(Sf + r * SWF + q * 32 + j * 4);
            vv[j] = v;
            ss += v.x * v.x + v.y * v.y + v.z * v.z + v.w * v.w;
        }
        ss += __shfl_xor_sync(0xffffffffu, ss, 1);
        ss += __shfl_xor_sync(0xffffffffu, ss, 2);
        float nrm = sqrtf(ss);
        float nc  = fmaxf(nrm, EPS);
        float fm  = tanhf(nc) / nc;
        int rg = row0 + r;
        if (rg < N) {
            #pragma unroll
            for (int j = 0; j < 8; j++) {
                float4 v = vv[j];
                v.x *= fm; v.y *= fm; v.z *= fm; v.w *= fm;
                ((float4*)outp)[rg * 32 + q * 8 + j] = v;
            }
        }
    }
}

// ---------------- launch ----------------
extern "C" void kernel_launch(void* const* d_in, const int* in_sizes, int n_in,
                              void* d_out, int out_size) {
    const float* x      = (const float*)d_in[0];
    const int*   ei     = (const int*)d_in[1];
    const float* w_msg1 = (const float*)d_in[2];
    const float* b_msg1 = (const float*)d_in[3];
    const float* w_msg2 = (const float*)d_in[4];
    const float* b_msg2 = (const float*)d_in[5];
    const float* w_upd1 = (const float*)d_in[6];
    const float* b_upd1 = (const float*)d_in[7];
    const float* w_upd2 = (const float*)d_in[8];
    const float* b_upd2 = (const float*)d_in[9];
    float* out = (float*)d_out;

    int N = in_sizes[0] / D;
    int E = in_sizes[1] / 2;

    cudaFuncSetAttribute(mlp_tc_kernel,
                         cudaFuncAttributeMaxDynamicSharedMemorySize, SMEM_DYN);

    prep_w_kernel<<<64, 256>>>(w_msg1, w_msg2, w_upd1, w_upd2);
    zero_hist_kernel<<<(N + 255) / 256, 256>>>(N);
    fill_kernel<<<(E + 255) / 256, 256>>>(ei, E);

    int mblocks = (N + TM - 1) / TM;
    mlp_tc_kernel<<<mblocks, 256, SMEM_DYN>>>(x, b_msg1, b_msg2, nullptr, N, 0);
    mlp_tc_kernel<<<mblocks, 256, SMEM_DYN>>>(nullptr, b_upd1, b_upd2, out, N, 1);
}

// round 10
// speedup vs baseline: 1.1416x; 1.1416x over previous
#include <cuda_runtime.h>
#include <cuda_fp16.h>
#include <cstdint>

#define D      128
#define TM     64
#define NMAX   50000
#define DEGMAX 128
#define EPS    1e-8f

#define ROWB  272           // bytes per fp16 tile row (136 halves)
#define SWF   132           // f32 staging stride

// ---------------- scratch (static device globals) ----------------
__device__ __half g_y[NMAX * D];            // fp16 (L2-resident, 12.8MB)
__device__ int    g_hist[NMAX];             // in-degree (atomic counters)
__device__ int    g_csr[NMAX * DEGMAX];     // padded neighbor buckets
// transposed fp16 weights: [mat][n][k]; mat: 0=msg1,1=msg2,2=upd1,3=upd2
__device__ __half g_wt[4 * D * D];

// ---------------- smem layout (bytes) — 70.7KB => 3 CTAs/SM ----------------
#define OFF_AH 0u            /* 64 x 272  = 17408 */
#define OFF_AL 17408u
#define OFF_W  34816u        /* 128 x 272 = 34816 (single W buffer) */
#define OFF_B1 69632u
#define OFF_B2 70144u
#define SMEM_DYN 70656u

// ---------------- PTX helpers ----------------
__device__ __forceinline__ uint32_t smem_u32(const void* p) {
    uint32_t a;
    asm("{ .reg .u64 t; cvta.to.shared.u64 t, %1; cvt.u32.u64 %0, t; }" : "=r"(a) : "l"(p));
    return a;
}
__device__ __forceinline__ void ldsm4(uint32_t* r, uint32_t addr) {
    asm volatile("ldmatrix.sync.aligned.m8n8.x4.shared.b16 {%0,%1,%2,%3}, [%4];"
        : "=r"(r[0]), "=r"(r[1]), "=r"(r[2]), "=r"(r[3]) : "r"(addr));
}
__device__ __forceinline__ void mma16816(float* c, const uint32_t* a,
                                         uint32_t b0, uint32_t b1) {
    asm("mma.sync.aligned.m16n8k16.row.col.f32.f16.f16.f32 "
        "{%0,%1,%2,%3}, {%4,%5,%6,%7}, {%8,%9}, {%0,%1,%2,%3};"
        : "+f"(c[0]), "+f"(c[1]), "+f"(c[2]), "+f"(c[3])
        : "r"(a[0]), "r"(a[1]), "r"(a[2]), "r"(a[3]), "r"(b0), "r"(b1));
}
__device__ __forceinline__ uint32_t packh2(__half a, __half b) {
    __half2 t = __halves2half2(a, b);
    return *(uint32_t*)&t;
}
#define CP_ASYNC16(dst, src) \
    asm volatile("cp.async.cg.shared.global [%0], [%1], 16;" :: "r"(dst), "l"(src))
#define CP_COMMIT() asm volatile("cp.async.commit_group;")
#define CP_WAIT0()  asm volatile("cp.async.wait_group 0;")

// 2-term fp16 split GEMM (M64 tile): acc += (Ah+Al) @ W^T
__device__ __forceinline__ void do_gemm(
    uint32_t sAH, uint32_t sAL, uint32_t sW,
    int wm, int wn, int lane, float acc[2][4][4])
{
    const uint32_t lrow = (uint32_t)(lane & 15) * ROWB + (uint32_t)(lane >> 4) * 16;
    const uint32_t aoff = (uint32_t)(wm * 32) * ROWB + lrow;
    const uint32_t woff = (uint32_t)(wn * 32) * ROWB + lrow;

    #pragma unroll
    for (int ks = 0; ks < 8; ks++) {
        const uint32_t kb = (uint32_t)ks * 32;
        uint32_t ah[2][4], al[2][4], wf[2][4];
        #pragma unroll
        for (int ms = 0; ms < 2; ms++) {
            ldsm4(ah[ms], sAH + aoff + ms * 16 * ROWB + kb);
            ldsm4(al[ms], sAL + aoff + ms * 16 * ROWB + kb);
        }
        #pragma unroll
        for (int np = 0; np < 2; np++)
            ldsm4(wf[np], sW + woff + np * 16 * ROWB + kb);
        #pragma unroll
        for (int np = 0; np < 2; np++)
            #pragma unroll
            for (int h = 0; h < 2; h++)
                #pragma unroll
                for (int ms = 0; ms < 2; ms++)
                    mma16816(acc[ms][np * 2 + h], ah[ms], wf[np][h], wf[np][h + 2]);
        #pragma unroll
        for (int np = 0; np < 2; np++)
            #pragma unroll
            for (int h = 0; h < 2; h++)
                #pragma unroll
                for (int ms = 0; ms < 2; ms++)
                    mma16816(acc[ms][np * 2 + h], al[ms], wf[np][h], wf[np][h + 2]);
    }
}

// ---------------- bucket-CSR build ----------------
__global__ void zero_hist_kernel(int n) {
    int i = blockIdx.x * blockDim.x + threadIdx.x;
    if (i < n) g_hist[i] = 0;
}
__global__ void fill_kernel(const int* __restrict__ ei, int E) {
    int e = blockIdx.x * blockDim.x + threadIdx.x;
    if (e < E) {
        int dst = ei[e];
        int src = ei[E + e];
        int pos = atomicAdd(&g_hist[dst], 1);
        if (pos < DEGMAX) g_csr[dst * DEGMAX + pos] = src;
    }
}

// transpose + fp16 convert of the 4 weight matrices
__global__ void prep_w_kernel(const float* __restrict__ w0, const float* __restrict__ w1,
                              const float* __restrict__ w2, const float* __restrict__ w3) {
    int g = blockIdx.x * blockDim.x + threadIdx.x;    // 0..16383
    int mat = g >> 12;
    int rem = g & 4095;
    int k = rem >> 5;
    int n4 = rem & 31;
    const float* W = (mat == 0) ? w0 : (mat == 1) ? w1 : (mat == 2) ? w2 : w3;
    float4 v = ((const float4*)W)[k * 32 + n4];
    float a[4] = {v.x, v.y, v.z, v.w};
    #pragma unroll
    for (int j = 0; j < 4; j++) {
        int n = n4 * 4 + j;
        g_wt[mat * D * D + n * D + k] = __float2half_rn(a[j]);
    }
}

// accumulate 4 fp16 pairs (uint2 = 4 halves) into float4
__device__ __forceinline__ void h2acc(float4& a, uint2 u) {
    __half2 p0 = *(__half2*)&u.x, p1 = *(__half2*)&u.y;
    float2 f0 = __half22float2(p0), f1 = __half22float2(p1);
    a.x += f0.x; a.y += f0.y; a.z += f1.x; a.w += f1.y;
}
__device__ __forceinline__ void f4add(float4& a, const float4 b) {
    a.x += b.x; a.y += b.y; a.z += b.z; a.w += b.w;
}

// ---------------- fused MLP via mma.sync (HMMA fp16), TM=64, 3 CTAs/SM ----------------
// mode 0: g_y = MLP1(logmap0(x))            (g_y stored fp16)
// mode 1: out = expmap0(MLP2(mean_{bucket} g_y[src]))
__global__ __launch_bounds__(256, 3) void mlp_tc_kernel(
    const float* __restrict__ xin,
    const float* __restrict__ B1v, const float* __restrict__ B2v,
    float* __restrict__ outp, int N, int mode)
{
    extern __shared__ char sb[];
    const uint32_t sbase = smem_u32(sb);
    float* B1s = (float*)(sb + OFF_B1);
    float* B2s = (float*)(sb + OFF_B2);

    const int tid  = threadIdx.x;
    const int wid  = tid >> 5;
    const int lane = tid & 31;
    const int gid  = lane >> 2;
    const int tig  = lane & 3;
    const int wm   = wid & 1;          // 2 x M32
    const int wn   = wid >> 1;         // 4 x N32
    const int row0 = blockIdx.x * TM;

    if (tid < 128) B1s[tid] = B1v[tid];
    else           B2s[tid - 128] = B2v[tid - 128];

    // ---- kick off W1 load via cp.async (overlaps input phase) ----
    {
        int m1 = mode * 2;
        const float4* s1 = (const float4*)(g_wt + m1 * D * D);
        #pragma unroll
        for (int it = 0; it < 8; it++) {
            int idx = tid + it * 256;          // 2048 float4
            int n = idx >> 4, c = idx & 15;
            CP_ASYNC16(sbase + OFF_W + n * ROWB + c * 16, (const void*)(s1 + idx));
        }
        CP_COMMIT();
    }

    // ---- input rows: logmap0(x) (mode 0) or bucket-gather mean (mode 1) ----
    {
        const float4* x4 = (const float4*)xin;
        const uint2*  y2 = (const uint2*)g_y;       // fp16 rows: 32 x uint2
        #pragma unroll 2
        for (int i = 0; i < 8; i++) {
            int r = wid * 8 + i;
            int rg = row0 + r;
            float4 v = make_float4(0.f, 0.f, 0.f, 0.f);
            if (rg < N) {
                if (mode == 0) {
                    v = x4[rg * 32 + lane];
                    float ss = v.x * v.x + v.y * v.y + v.z * v.z + v.w * v.w;
                    #pragma unroll
                    for (int m = 16; m >= 1; m >>= 1) ss += __shfl_xor_sync(0xffffffffu, ss, m);
                    float nrm = sqrtf(ss);
                    float nc  = fminf(fmaxf(nrm, EPS), 1.0f - 1e-5f);
                    float f   = atanhf(nc) / nc;
                    v.x *= f; v.y *= f; v.z *= f; v.w *= f;
                } else {
                    const int* nb = g_csr + rg * DEGMAX;
                    int deg = g_hist[rg];
                    if (deg > DEGMAX) deg = DEGMAX;
                    float4 v1 = make_float4(0.f, 0.f, 0.f, 0.f);
                    float4 v2 = make_float4(0.f, 0.f, 0.f, 0.f);
                    float4 v3 = make_float4(0.f, 0.f, 0.f, 0.f);
                    int j = 0;
                    for (; j + 4 <= deg; j += 4) {
                        int s0 = nb[j], s1 = nb[j + 1], s2 = nb[j + 2], s3 = nb[j + 3];
                        h2acc(v,  y2[s0 * 32 + lane]);
                        h2acc(v1, y2[s1 * 32 + lane]);
                        h2acc(v2, y2[s2 * 32 + lane]);
                        h2acc(v3, y2[s3 * 32 + lane]);
                    }
                    for (; j < deg; j++)
                        h2acc(v, y2[nb[j] * 32 + lane]);
                    f4add(v1, v2); f4add(v, v3); f4add(v, v1);
                    float inv = 1.0f / ((float)g_hist[rg] + EPS);
                    v.x *= inv; v.y *= inv; v.z *= inv; v.w *= inv;
                }
            }
            // fp16 hi/lo split of A
            __half h0 = __float2half_rn(v.x), h1 = __float2half_rn(v.y);
            __half h2 = __float2half_rn(v.z), h3 = __float2half_rn(v.w);
            __half l0 = __float2half_rn(v.x - __half2float(h0));
            __half l1 = __float2half_rn(v.y - __half2float(h1));
            __half l2 = __float2half_rn(v.z - __half2float(h2));
            __half l3 = __float2half_rn(v.w - __half2float(h3));
            *(uint2*)(sb + OFF_AH + r * ROWB + lane * 8) =
                make_uint2(packh2(h0, h1), packh2(h2, h3));
            *(uint2*)(sb + OFF_AL + r * ROWB + lane * 8) =
                make_uint2(packh2(l0, l1), packh2(l2, l3));
        }
    }
    CP_WAIT0();
    __syncthreads();

    float acc[2][4][4];

    // ---- GEMM1 ----
    #pragma unroll
    for (int ms = 0; ms < 2; ms++)
        #pragma unroll
        for (int ns = 0; ns < 4; ns++)
            #pragma unroll
            for (int j = 0; j < 4; j++) acc[ms][ns][j] = 0.f;
    do_gemm(sbase + OFF_AH, sbase + OFF_AL, sbase + OFF_W, wm, wn, lane, acc);
    __syncthreads();      // all reads of W1 and A complete

    // ---- kick W2 into the same W buffer (overlaps epilogue1) ----
    {
        int m2 = mode * 2 + 1;
        const float4* s2 = (const float4*)(g_wt + m2 * D * D);
        #pragma unroll
        for (int it = 0; it < 8; it++) {
            int idx = tid + it * 256;
            int n = idx >> 4, c = idx & 15;
            CP_ASYNC16(sbase + OFF_W + n * ROWB + c * 16, (const void*)(s2 + idx));
        }
        CP_COMMIT();
    }

    // ---- epilogue1: T = relu(acc + B1) -> Ah/Al (fp16 hi/lo) ----
    #pragma unroll
    for (int ms = 0; ms < 2; ms++) {
        int r = wm * 32 + ms * 16 + gid;
        #pragma unroll
        for (int ns = 0; ns < 4; ns++) {
            int col = wn * 32 + ns * 8 + tig * 2;
            float b0 = B1s[col], b1 = B1s[col + 1];
            float v0 = fmaxf(acc[ms][ns][0] + b0, 0.f);
            float v1 = fmaxf(acc[ms][ns][1] + b1, 0.f);
            float v2 = fmaxf(acc[ms][ns][2] + b0, 0.f);
            float v3 = fmaxf(acc[ms][ns][3] + b1, 0.f);
            __half a0 = __float2half_rn(v0), a1 = __float2half_rn(v1);
            __half a2 = __float2half_rn(v2), a3 = __float2half_rn(v3);
            __half c0 = __float2half_rn(v0 - __half2float(a0));
            __half c1 = __float2half_rn(v1 - __half2float(a1));
            __half c2 = __float2half_rn(v2 - __half2float(a2));
            __half c3 = __float2half_rn(v3 - __half2float(a3));
            *(uint32_t*)(sb + OFF_AH + r * ROWB + col * 2)       = packh2(a0, a1);
            *(uint32_t*)(sb + OFF_AL + r * ROWB + col * 2)       = packh2(c0, c1);
            *(uint32_t*)(sb + OFF_AH + (r + 8) * ROWB + col * 2) = packh2(a2, a3);
            *(uint32_t*)(sb + OFF_AL + (r + 8) * ROWB + col * 2) = packh2(c2, c3);
        }
    }
    CP_WAIT0();
    __syncthreads();

    // ---- GEMM2 ----
    #pragma unroll
    for (int ms = 0; ms < 2; ms++)
        #pragma unroll
        for (int ns = 0; ns < 4; ns++)
            #pragma unroll
            for (int j = 0; j < 4; j++) acc[ms][ns][j] = 0.f;
    do_gemm(sbase + OFF_AH, sbase + OFF_AL, sbase + OFF_W, wm, wn, lane, acc);

    if (mode == 0) {
        // write g_y in fp16 (half2 per 2 cols)
        __half2* yh = (__half2*)g_y;
        #pragma unroll
        for (int ms = 0; ms < 2; ms++) {
            int r = wm * 32 + ms * 16 + gid;
            #pragma unroll
            for (int ns = 0; ns < 4; ns++) {
                int col = wn * 32 + ns * 8 + tig * 2;
                float b0 = B2s[col], b1 = B2s[col + 1];
                int rg = row0 + r;
                if (rg < N)
                    yh[rg * 64 + (col >> 1)] =
                        __floats2half2_rn(acc[ms][ns][0] + b0, acc[ms][ns][1] + b1);
                if (rg + 8 < N)
                    yh[(rg + 8) * 64 + (col >> 1)] =
                        __floats2half2_rn(acc[ms][ns][2] + b0, acc[ms][ns][3] + b1);
            }
        }
    } else {
        __syncthreads();       // W reads done; reuse W region as f32 staging
        float* Sf = (float*)(sb + OFF_W);         // 64 x 132 f32 = 33.8KB fits 34.8KB
        #pragma unroll
        for (int ms = 0; ms < 2; ms++) {
            int r = wm * 32 + ms * 16 + gid;
            #pragma unroll
            for (int ns = 0; ns < 4; ns++) {
                int col = wn * 32 + ns * 8 + tig * 2;
                float b0 = B2s[col], b1 = B2s[col + 1];
                *(float2*)(Sf + r * SWF + col) =
                    make_float2(acc[ms][ns][0] + b0, acc[ms][ns][1] + b1);
                *(float2*)(Sf + (r + 8) * SWF + col) =
                    make_float2(acc[ms][ns][2] + b0, acc[ms][ns][3] + b1);
            }
        }
        __syncthreads();
        // expmap0: 4 threads per row
        int r = tid >> 2, q = tid & 3;
        float ss = 0.f;
        float4 vv[8];
        #pragma unroll
        for (int j = 0; j < 8; j++) {
            float4 v = *(float4*)(Sf + r * SWF + q * 32 + j * 4);
            vv[j] = v;
            ss += v.x * v.x + v.y * v.y + v.z * v.z + v.w * v.w;
        }
        ss += __shfl_xor_sync(0xffffffffu, ss, 1);
        ss += __shfl_xor_sync(0xffffffffu, ss, 2);
        float nrm = sqrtf(ss);
        float nc  = fmaxf(nrm, EPS);
        float fm  = tanhf(nc) / nc;
        int rg = row0 + r;
        if (rg < N) {
            #pragma unroll
            for (int j = 0; j < 8; j++) {
                float4 v = vv[j];
                v.x *= fm; v.y *= fm; v.z *= fm; v.w *= fm;
                ((float4*)outp)[rg * 32 + q * 8 + j] = v;
            }
        }
    }
}

// ---------------- launch ----------------
extern "C" void kernel_launch(void* const* d_in, const int* in_sizes, int n_in,
                              void* d_out, int out_size) {
    const float* x      = (const float*)d_in[0];
    const int*   ei     = (const int*)d_in[1];
    const float* w_msg1 = (const float*)d_in[2];
    const float* b_msg1 = (const float*)d_in[3];
    const float* w_msg2 = (const float*)d_in[4];
    const float* b_msg2 = (const float*)d_in[5];
    const float* w_upd1 = (const float*)d_in[6];
    const float* b_upd1 = (const float*)d_in[7];
    const float* w_upd2 = (const float*)d_in[8];
    const float* b_upd2 = (const float*)d_in[9];
    float* out = (float*)d_out;

    int N = in_sizes[0] / D;
    int E = in_sizes[1] / 2;

    cudaFuncSetAttribute(mlp_tc_kernel,
                         cudaFuncAttributeMaxDynamicSharedMemorySize, SMEM_DYN);

    prep_w_kernel<<<64, 256>>>(w_msg1, w_msg2, w_upd1, w_upd2);
    zero_hist_kernel<<<(N + 255) / 256, 256>>>(N);
    fill_kernel<<<(E + 255) / 256, 256>>>(ei, E);

    int mblocks = (N + TM - 1) / TM;
    mlp_tc_kernel<<<mblocks, 256, SMEM_DYN>>>(x, b_msg1, b_msg2, nullptr, N, 0);
    mlp_tc_kernel<<<mblocks, 256, SMEM_DYN>>>(nullptr, b_upd1, b_upd2, out, N, 1);
}

// round 11
// speedup vs baseline: 1.2193x; 1.0681x over previous
#include <cuda_runtime.h>
#include <cuda_fp16.h>
#include <cstdint>

#define D      128
#define TM     64
#define NMAX   50000
#define DEGMAX 128
#define EPS    1e-8f

#define ROWB  272           // bytes per fp16 tile row (136 halves)
#define SWF   132           // f32 staging stride

// ---------------- scratch (static device globals) ----------------
__device__ __half g_y[NMAX * D];            // fp16 (L2-resident, 12.8MB)
__device__ int    g_hist[NMAX];             // in-degree (atomic counters)
__device__ int    g_csr[NMAX * DEGMAX];     // padded neighbor buckets
// transposed fp16 weights: [mat][n][k]; mat: 0=msg1,1=msg2,2=upd1,3=upd2
__device__ __half g_wt[4 * D * D];

// ---------------- smem layout (bytes) — 53.2KB => 4 CTAs/SM ----------------
#define OFF_A  0u            /* 64 x 272  = 17408 */
#define OFF_W  17408u        /* 128 x 272 = 34816 (single W buffer) */
#define OFF_B1 52224u
#define OFF_B2 52736u
#define SMEM_DYN 53248u

// ---------------- PTX helpers ----------------
__device__ __forceinline__ uint32_t smem_u32(const void* p) {
    uint32_t a;
    asm("{ .reg .u64 t; cvta.to.shared.u64 t, %1; cvt.u32.u64 %0, t; }" : "=r"(a) : "l"(p));
    return a;
}
__device__ __forceinline__ void ldsm4(uint32_t* r, uint32_t addr) {
    asm volatile("ldmatrix.sync.aligned.m8n8.x4.shared.b16 {%0,%1,%2,%3}, [%4];"
        : "=r"(r[0]), "=r"(r[1]), "=r"(r[2]), "=r"(r[3]) : "r"(addr));
}
__device__ __forceinline__ void mma16816(float* c, const uint32_t* a,
                                         uint32_t b0, uint32_t b1) {
    asm("mma.sync.aligned.m16n8k16.row.col.f32.f16.f16.f32 "
        "{%0,%1,%2,%3}, {%4,%5,%6,%7}, {%8,%9}, {%0,%1,%2,%3};"
        : "+f"(c[0]), "+f"(c[1]), "+f"(c[2]), "+f"(c[3])
        : "r"(a[0]), "r"(a[1]), "r"(a[2]), "r"(a[3]), "r"(b0), "r"(b1));
}
__device__ __forceinline__ uint32_t packh2(__half a, __half b) {
    __half2 t = __halves2half2(a, b);
    return *(uint32_t*)&t;
}
#define CP_ASYNC16(dst, src) \
    asm volatile("cp.async.cg.shared.global [%0], [%1], 16;" :: "r"(dst), "l"(src))
#define CP_COMMIT() asm volatile("cp.async.commit_group;")
#define CP_WAIT0()  asm volatile("cp.async.wait_group 0;")

// plain fp16 GEMM (M64 tile): acc += A @ W^T
__device__ __forceinline__ void do_gemm(
    uint32_t sA, uint32_t sW, int wm, int wn, int lane, float acc[2][4][4])
{
    const uint32_t lrow = (uint32_t)(lane & 15) * ROWB + (uint32_t)(lane >> 4) * 16;
    const uint32_t aoff = (uint32_t)(wm * 32) * ROWB + lrow;
    const uint32_t woff = (uint32_t)(wn * 32) * ROWB + lrow;

    #pragma unroll
    for (int ks = 0; ks < 8; ks++) {
        const uint32_t kb = (uint32_t)ks * 32;
        uint32_t af[2][4], wf[2][4];
        #pragma unroll
        for (int ms = 0; ms < 2; ms++)
            ldsm4(af[ms], sA + aoff + ms * 16 * ROWB + kb);
        #pragma unroll
        for (int np = 0; np < 2; np++)
            ldsm4(wf[np], sW + woff + np * 16 * ROWB + kb);
        #pragma unroll
        for (int np = 0; np < 2; np++)
            #pragma unroll
            for (int h = 0; h < 2; h++)
                #pragma unroll
                for (int ms = 0; ms < 2; ms++)
                    mma16816(acc[ms][np * 2 + h], af[ms], wf[np][h], wf[np][h + 2]);
    }
}

// transpose + fp16 convert of the 4 weight matrices; also zero g_hist
__global__ void prep_w_kernel(const float* __restrict__ w0, const float* __restrict__ w1,
                              const float* __restrict__ w2, const float* __restrict__ w3,
                              int N) {
    int g = blockIdx.x * blockDim.x + threadIdx.x;    // 0..16383
    for (int i = g; i < N; i += 16384) g_hist[i] = 0;
    int mat = g >> 12;
    int rem = g & 4095;
    int k = rem >> 5;
    int n4 = rem & 31;
    const float* W = (mat == 0) ? w0 : (mat == 1) ? w1 : (mat == 2) ? w2 : w3;
    float4 v = ((const float4*)W)[k * 32 + n4];
    float a[4] = {v.x, v.y, v.z, v.w};
    #pragma unroll
    for (int j = 0; j < 4; j++) {
        int n = n4 * 4 + j;
        g_wt[mat * D * D + n * D + k] = __float2half_rn(a[j]);
    }
}

// accumulate 4 fp16 pairs (uint2 = 4 halves) into float4
__device__ __forceinline__ void h2acc(float4& a, uint2 u) {
    __half2 p0 = *(__half2*)&u.x, p1 = *(__half2*)&u.y;
    float2 f0 = __half22float2(p0), f1 = __half22float2(p1);
    a.x += f0.x; a.y += f0.y; a.z += f1.x; a.w += f1.y;
}
__device__ __forceinline__ void f4add(float4& a, const float4 b) {
    a.x += b.x; a.y += b.y; a.z += b.z; a.w += b.w;
}

// ---------------- fused MLP via mma.sync (HMMA fp16), TM=64, 4 CTAs/SM ----------------
// mode 0: fill CSR buckets (grid-stride), then g_y = MLP1(logmap0(x))
// mode 1: out = expmap0(MLP2(mean_{bucket} g_y[src]))
__global__ __launch_bounds__(256, 4) void mlp_tc_kernel(
    const float* __restrict__ xin, const int* __restrict__ ei, int E,
    const float* __restrict__ B1v, const float* __restrict__ B2v,
    float* __restrict__ outp, int N, int mode)
{
    extern __shared__ char sb[];
    const uint32_t sbase = smem_u32(sb);
    float* B1s = (float*)(sb + OFF_B1);
    float* B2s = (float*)(sb + OFF_B2);

    const int tid  = threadIdx.x;
    const int wid  = tid >> 5;
    const int lane = tid & 31;
    const int gid  = lane >> 2;
    const int tig  = lane & 3;
    const int wm   = wid & 1;          // 2 x M32
    const int wn   = wid >> 1;         // 4 x N32
    const int row0 = blockIdx.x * TM;

    if (tid < 128) B1s[tid] = B1v[tid];
    else           B2s[tid - 128] = B2v[tid - 128];

    // ---- kick off W1 load via cp.async (overlaps fill + input phase) ----
    {
        int m1 = mode * 2;
        const float4* s1 = (const float4*)(g_wt + m1 * D * D);
        #pragma unroll
        for (int it = 0; it < 8; it++) {
            int idx = tid + it * 256;          // 2048 float4
            int n = idx >> 4, c = idx & 15;
            CP_ASYNC16(sbase + OFF_W + n * ROWB + c * 16, (const void*)(s1 + idx));
        }
        CP_COMMIT();
    }

    // ---- mode 0: CSR bucket fill (grid-stride over edges) ----
    if (mode == 0) {
        int stride = gridDim.x * 256;
        for (int e = blockIdx.x * 256 + tid; e < E; e += stride) {
            int dst = ei[e];
            int src = ei[E + e];
            int pos = atomicAdd(&g_hist[dst], 1);
            if (pos < DEGMAX) g_csr[dst * DEGMAX + pos] = src;
        }
    }

    // ---- input rows: logmap0(x) (mode 0) or bucket-gather mean (mode 1) ----
    {
        const float4* x4 = (const float4*)xin;
        const uint2*  y2 = (const uint2*)g_y;       // fp16 rows: 32 x uint2
        #pragma unroll 2
        for (int i = 0; i < 8; i++) {
            int r = wid * 8 + i;
            int rg = row0 + r;
            float4 v = make_float4(0.f, 0.f, 0.f, 0.f);
            if (rg < N) {
                if (mode == 0) {
                    v = x4[rg * 32 + lane];
                    float ss = v.x * v.x + v.y * v.y + v.z * v.z + v.w * v.w;
                    #pragma unroll
                    for (int m = 16; m >= 1; m >>= 1) ss += __shfl_xor_sync(0xffffffffu, ss, m);
                    float nrm = sqrtf(ss);
                    float nc  = fminf(fmaxf(nrm, EPS), 1.0f - 1e-5f);
                    float f   = atanhf(nc) / nc;
                    v.x *= f; v.y *= f; v.z *= f; v.w *= f;
                } else {
                    const int* nb = g_csr + rg * DEGMAX;
                    int deg = g_hist[rg];
                    if (deg > DEGMAX) deg = DEGMAX;
                    float4 v1 = make_float4(0.f, 0.f, 0.f, 0.f);
                    float4 v2 = make_float4(0.f, 0.f, 0.f, 0.f);
                    float4 v3 = make_float4(0.f, 0.f, 0.f, 0.f);
                    int j = 0;
                    for (; j + 4 <= deg; j += 4) {
                        int s0 = nb[j], s1 = nb[j + 1], s2 = nb[j + 2], s3 = nb[j + 3];
                        h2acc(v,  y2[s0 * 32 + lane]);
                        h2acc(v1, y2[s1 * 32 + lane]);
                        h2acc(v2, y2[s2 * 32 + lane]);
                        h2acc(v3, y2[s3 * 32 + lane]);
                    }
                    for (; j < deg; j++)
                        h2acc(v, y2[nb[j] * 32 + lane]);
                    f4add(v1, v2); f4add(v, v3); f4add(v, v1);
                    float inv = 1.0f / ((float)g_hist[rg] + EPS);
                    v.x *= inv; v.y *= inv; v.z *= inv; v.w *= inv;
                }
            }
            *(uint2*)(sb + OFF_A + r * ROWB + lane * 8) =
                make_uint2(packh2(__float2half_rn(v.x), __float2half_rn(v.y)),
                           packh2(__float2half_rn(v.z), __float2half_rn(v.w)));
        }
    }
    CP_WAIT0();
    __syncthreads();

    float acc[2][4][4];

    // ---- GEMM1 ----
    #pragma unroll
    for (int ms = 0; ms < 2; ms++)
        #pragma unroll
        for (int ns = 0; ns < 4; ns++)
            #pragma unroll
            for (int j = 0; j < 4; j++) acc[ms][ns][j] = 0.f;
    do_gemm(sbase + OFF_A, sbase + OFF_W, wm, wn, lane, acc);
    __syncthreads();      // all reads of W1 and A complete

    // ---- kick W2 into the same W buffer (overlaps epilogue1) ----
    {
        int m2 = mode * 2 + 1;
        const float4* s2 = (const float4*)(g_wt + m2 * D * D);
        #pragma unroll
        for (int it = 0; it < 8; it++) {
            int idx = tid + it * 256;
            int n = idx >> 4, c = idx & 15;
            CP_ASYNC16(sbase + OFF_W + n * ROWB + c * 16, (const void*)(s2 + idx));
        }
        CP_COMMIT();
    }

    // ---- epilogue1: T = relu(acc + B1) -> A (fp16) ----
    #pragma unroll
    for (int ms = 0; ms < 2; ms++) {
        int r = wm * 32 + ms * 16 + gid;
        #pragma unroll
        for (int ns = 0; ns < 4; ns++) {
            int col = wn * 32 + ns * 8 + tig * 2;
            float b0 = B1s[col], b1 = B1s[col + 1];
            float v0 = fmaxf(acc[ms][ns][0] + b0, 0.f);
            float v1 = fmaxf(acc[ms][ns][1] + b1, 0.f);
            float v2 = fmaxf(acc[ms][ns][2] + b0, 0.f);
            float v3 = fmaxf(acc[ms][ns][3] + b1, 0.f);
            *(uint32_t*)(sb + OFF_A + r * ROWB + col * 2) =
                packh2(__float2half_rn(v0), __float2half_rn(v1));
            *(uint32_t*)(sb + OFF_A + (r + 8) * ROWB + col * 2) =
                packh2(__float2half_rn(v2), __float2half_rn(v3));
        }
    }
    CP_WAIT0();
    __syncthreads();

    // ---- GEMM2 ----
    #pragma unroll
    for (int ms = 0; ms < 2; ms++)
        #pragma unroll
        for (int ns = 0; ns < 4; ns++)
            #pragma unroll
            for (int j = 0; j < 4; j++) acc[ms][ns][j] = 0.f;
    do_gemm(sbase + OFF_A, sbase + OFF_W, wm, wn, lane, acc);

    if (mode == 0) {
        // write g_y in fp16 (half2 per 2 cols)
        __half2* yh = (__half2*)g_y;
        #pragma unroll
        for (int ms = 0; ms < 2; ms++) {
            int r = wm * 32 + ms * 16 + gid;
            #pragma unroll
            for (int ns = 0; ns < 4; ns++) {
                int col = wn * 32 + ns * 8 + tig * 2;
                float b0 = B2s[col], b1 = B2s[col + 1];
                int rg = row0 + r;
                if (rg < N)
                    yh[rg * 64 + (col >> 1)] =
                        __floats2half2_rn(acc[ms][ns][0] + b0, acc[ms][ns][1] + b1);
                if (rg + 8 < N)
                    yh[(rg + 8) * 64 + (col >> 1)] =
                        __floats2half2_rn(acc[ms][ns][2] + b0, acc[ms][ns][3] + b1);
            }
        }
    } else {
        __syncthreads();       // W reads done; reuse W region as f32 staging
        float* Sf = (float*)(sb + OFF_W);         // 64 x 132 f32 = 33.8KB fits 34.8KB
        #pragma unroll
        for (int ms = 0; ms < 2; ms++) {
            int r = wm * 32 + ms * 16 + gid;
            #pragma unroll
            for (int ns = 0; ns < 4; ns++) {
                int col = wn * 32 + ns * 8 + tig * 2;
                float b0 = B2s[col], b1 = B2s[col + 1];
                *(float2*)(Sf + r * SWF + col) =
                    make_float2(acc[ms][ns][0] + b0, acc[ms][ns][1] + b1);
                *(float2*)(Sf + (r + 8) * SWF + col) =
                    make_float2(acc[ms][ns][2] + b0, acc[ms][ns][3] + b1);
            }
        }
        __syncthreads();
        // expmap0: 4 threads per row
        int r = tid >> 2, q = tid & 3;
        float ss = 0.f;
        float4 vv[8];
        #pragma unroll
        for (int j = 0; j < 8; j++) {
            float4 v = *(float4*)(Sf + r * SWF + q * 32 + j * 4);
            vv[j] = v;
            ss += v.x * v.x + v.y * v.y + v.z * v.z + v.w * v.w;
        }
        ss += __shfl_xor_sync(0xffffffffu, ss, 1);
        ss += __shfl_xor_sync(0xffffffffu, ss, 2);
        float nrm = sqrtf(ss);
        float nc  = fmaxf(nrm, EPS);
        float fm  = tanhf(nc) / nc;
        int rg = row0 + r;
        if (rg < N) {
            #pragma unroll
            for (int j = 0; j < 8; j++) {
                float4 v = vv[j];
                v.x *= fm; v.y *= fm; v.z *= fm; v.w *= fm;
                ((float4*)outp)[rg * 32 + q * 8 + j] = v;
            }
        }
    }
}

// ---------------- launch ----------------
extern "C" void kernel_launch(void* const* d_in, const int* in_sizes, int n_in,
                              void* d_out, int out_size) {
    const float* x      = (const float*)d_in[0];
    const int*   ei     = (const int*)d_in[1];
    const float* w_msg1 = (const float*)d_in[2];
    const float* b_msg1 = (const float*)d_in[3];
    const float* w_msg2 = (const float*)d_in[4];
    const float* b_msg2 = (const float*)d_in[5];
    const float* w_upd1 = (const float*)d_in[6];
    const float* b_upd1 = (const float*)d_in[7];
    const float* w_upd2 = (const float*)d_in[8];
    const float* b_upd2 = (const float*)d_in[9];
    float* out = (float*)d_out;

    int N = in_sizes[0] / D;
    int E = in_sizes[1] / 2;

    cudaFuncSetAttribute(mlp_tc_kernel,
                         cudaFuncAttributeMaxDynamicSharedMemorySize, SMEM_DYN);

    prep_w_kernel<<<64, 256>>>(w_msg1, w_msg2, w_upd1, w_upd2, N);

    int mblocks = (N + TM - 1) / TM;
    // mode 0 also fills CSR buckets at its start (overlaps cp.async W load)
    mlp_tc_kernel<<<mblocks, 256, SMEM_DYN>>>(x, ei, E, b_msg1, b_msg2, nullptr, N, 0);
    mlp_tc_kernel<<<mblocks, 256, SMEM_DYN>>>(nullptr, nullptr, 0, b_upd1, b_upd2, out, N, 1);
}